// round 5
// baseline (speedup 1.0000x reference)
#include <cuda_runtime.h>

// Problem constants (fixed shapes from the reference)
constexpr int Bn = 4;       // batch
constexpr int Nn = 16384;   // points per cloud
constexpr int Pn = 1024;    // npoint (FPS samples)
constexpr int Sn = 64;      // nsample (ball query)

// Scratch: ball query indices (B,P,S). 1 MB.
__device__ int g_ball_idx[Bn * Pn * Sn];

// ---------------------------------------------------------------------------
// Kernel 1: Furthest Point Sampling — one block per batch.
// xyz kept in shared memory (192 KB), per-thread mindist[16] in registers.
// Distance math is NON-contracted (__fmul_rn/__fadd_rn) to match XLA bitwise;
// argmax tie-break = first (smallest) index, matching jnp.argmax.
// ---------------------------------------------------------------------------
__global__ __launch_bounds__(1024, 1)
void fps_kernel(const float* __restrict__ xyz, float* __restrict__ new_xyz)
{
    const int b = blockIdx.x;
    const float* pts = xyz + (size_t)b * Nn * 3;

    extern __shared__ float sm[];
    float2* sxy = reinterpret_cast<float2*>(sm);   // [Nn] (x,y)
    float*  sz  = sm + 2 * Nn;                     // [Nn] z

    __shared__ float s_val[32];
    __shared__ int   s_idx[32];
    __shared__ int   s_sel;

    const int tid  = threadIdx.x;
    const int lane = tid & 31;
    const int wid  = tid >> 5;

    // Stage the cloud into shared memory (conflict-free strided layout).
    for (int p = tid; p < Nn; p += 1024) {
        float x = pts[p * 3 + 0];
        float y = pts[p * 3 + 1];
        float z = pts[p * 3 + 2];
        sxy[p] = make_float2(x, y);
        sz[p]  = z;
    }

    float md[16];
#pragma unroll
    for (int k = 0; k < 16; ++k) md[k] = 1e10f;   // matches jnp 1e10 init

    __syncthreads();

    // First selected point is index 0.
    float qx = sxy[0].x, qy = sxy[0].y, qz = sz[0];
    if (tid == 0) {
        float* o = new_xyz + (size_t)b * Pn * 3;
        o[0] = qx; o[1] = qy; o[2] = qz;
    }

    for (int it = 1; it < Pn; ++it) {
        float bv = -1.0f;
        int   bi = 0;
#pragma unroll
        for (int k = 0; k < 16; ++k) {
            const int p = (k << 10) + tid;         // ascending global index
            float2 v = sxy[p];
            float  zz = sz[p];
            float dx = __fadd_rn(v.x, -qx);
            float dy = __fadd_rn(v.y, -qy);
            float dz = __fadd_rn(zz,  -qz);
            float d  = __fadd_rn(__fadd_rn(__fmul_rn(dx, dx), __fmul_rn(dy, dy)),
                                 __fmul_rn(dz, dz));
            float m  = fminf(md[k], d);
            md[k] = m;
            if (m > bv) { bv = m; bi = p; }        // strict > : first-max wins
        }
        // Warp argmax (larger value wins; tie -> smaller index)
#pragma unroll
        for (int off = 16; off > 0; off >>= 1) {
            float ov = __shfl_down_sync(0xffffffffu, bv, off);
            int   oi = __shfl_down_sync(0xffffffffu, bi, off);
            if (ov > bv || (ov == bv && oi < bi)) { bv = ov; bi = oi; }
        }
        if (lane == 0) { s_val[wid] = bv; s_idx[wid] = bi; }
        __syncthreads();
        if (wid == 0) {
            bv = s_val[lane];
            bi = s_idx[lane];
#pragma unroll
            for (int off = 16; off > 0; off >>= 1) {
                float ov = __shfl_down_sync(0xffffffffu, bv, off);
                int   oi = __shfl_down_sync(0xffffffffu, bi, off);
                if (ov > bv || (ov == bv && oi < bi)) { bv = ov; bi = oi; }
            }
            if (lane == 0) s_sel = bi;
        }
        __syncthreads();

        const int sel = s_sel;
        float2 qv = sxy[sel];                       // smem broadcast read
        qx = qv.x; qy = qv.y; qz = sz[sel];
        if (tid == 0) {
            float* o = new_xyz + ((size_t)b * Pn + it) * 3;
            o[0] = qx; o[1] = qy; o[2] = qz;
        }
    }
}

// ---------------------------------------------------------------------------
// Kernel 2: Ball query — one warp per center, 8 centers (same batch) per block.
// First nsample in-ball indices in ascending order; pad with first hit (0 if
// none). Early exit once 64 found. Exact (non-contracted) distance + strict <.
// ---------------------------------------------------------------------------
__global__ __launch_bounds__(256)
void ballq_kernel(const float* __restrict__ xyz, const float* __restrict__ new_xyz)
{
    const int wglobal = blockIdx.x * 8 + (threadIdx.x >> 5);  // center id 0..4095
    const int b    = wglobal >> 10;
    const int lane = threadIdx.x & 31;

    const float* pts = xyz + (size_t)b * Nn * 3;
    const float* c   = new_xyz + (size_t)wglobal * 3;
    const float cx = c[0], cy = c[1], cz = c[2];
    int* oidx = g_ball_idx + (size_t)wglobal * Sn;

    const float R2 = (float)(0.3 * 0.3);   // same double->f32 path as JAX

    int  cnt   = 0;
    int  first = 0;
    bool have  = false;

    for (int base = 0; base < Nn; base += 32) {
        const int j = base + lane;
        float x = pts[j * 3 + 0];
        float y = pts[j * 3 + 1];
        float z = pts[j * 3 + 2];
        float dx = __fadd_rn(cx, -x);
        float dy = __fadd_rn(cy, -y);
        float dz = __fadd_rn(cz, -z);
        float d  = __fadd_rn(__fadd_rn(__fmul_rn(dx, dx), __fmul_rn(dy, dy)),
                             __fmul_rn(dz, dz));
        bool in = d < R2;
        unsigned m = __ballot_sync(0xffffffffu, in);
        if (m) {
            if (!have) { first = base + (__ffs(m) - 1); have = true; }
            if (in) {
                int pos = cnt + __popc(m & ((1u << lane) - 1u));
                if (pos < Sn) oidx[pos] = j;
            }
            cnt += __popc(m);
            if (cnt >= Sn) break;
        }
    }
    if (cnt < Sn) {
        for (int s = cnt + lane; s < Sn; s += 32) oidx[s] = first;  // 0 if none
    }
}

// ---------------------------------------------------------------------------
// Kernel 3: gather + MLP(6->64->64->128, relu) + max over samples.
// Block = 128 threads = 2 centers, thread = one sample.
// Weights in smem (W1,W3 transposed; W3 rows padded to 132 floats for
// conflict-free transpose + 16B-aligned float4 broadcast reads).
// Layers 2+3 fused: h2_i consumed immediately, h1[64]+h3[128] in registers.
// ---------------------------------------------------------------------------
constexpr int SW_FLOATS = 384 + 64 + 4096 + 64 + 64 * 132 + 128;  // 13184

__global__ __launch_bounds__(128)
void group_mlp_kernel(const float* __restrict__ xyz, const float* __restrict__ features,
                      const float* __restrict__ W1, const float* __restrict__ b1,
                      const float* __restrict__ W2, const float* __restrict__ b2,
                      const float* __restrict__ W3, const float* __restrict__ b3,
                      const float* __restrict__ new_xyz, float* __restrict__ out_feat)
{
    extern __shared__ float sw[];
    float* w1t = sw;                 // [6][64]   w1t[c*64+o] = W1[o][c]
    float* b1s = w1t + 384;          // [64]
    float* w2s = b1s + 64;           // [64][64]  row i = W2[i][:]
    float* b2s = w2s + 4096;         // [64]
    float* w3t = b2s + 64;           // [64][132] w3t[i*132+o] = W3[o][i]
    float* b3s = w3t + 64 * 132;     // [128]

    const int tid = threadIdx.x;

    for (int j = tid; j < 384; j += 128) {
        int cc = j >> 6, o = j & 63;
        w1t[j] = W1[o * 6 + cc];
    }
    if (tid < 64)  b1s[tid] = b1[tid];
    for (int j = tid; j < 4096; j += 128) w2s[j] = W2[j];
    if (tid < 64)  b2s[tid] = b2[tid];
    for (int j = tid; j < 8192; j += 128) {          // coalesced read, ~4-way STS
        int i = j & 63, o = j >> 6;
        w3t[i * 132 + o] = W3[j];
    }
    if (tid < 128) b3s[tid] = b3[tid];
    __syncthreads();

    const int cl = tid >> 6;                  // which of the 2 centers
    const int s  = tid & 63;                  // sample id
    const int center = blockIdx.x * 2 + cl;
    const int b  = center >> 10;
    const int gi = g_ball_idx[center * Sn + s];

    const float* pb = xyz      + (size_t)b * Nn * 3;
    const float* fb = features + (size_t)b * Nn * 3;
    const float* c  = new_xyz  + (size_t)center * 3;

    float g[6];
    g[0] = pb[gi * 3 + 0] - c[0];
    g[1] = pb[gi * 3 + 1] - c[1];
    g[2] = pb[gi * 3 + 2] - c[2];
    g[3] = fb[gi * 3 + 0];
    g[4] = fb[gi * 3 + 1];
    g[5] = fb[gi * 3 + 2];

    // ---- layer 1 ----
    float h1[64];
#pragma unroll
    for (int o = 0; o < 64; o += 4) {
        float4 bv = *reinterpret_cast<const float4*>(b1s + o);
        h1[o] = bv.x; h1[o + 1] = bv.y; h1[o + 2] = bv.z; h1[o + 3] = bv.w;
    }
#pragma unroll
    for (int cc = 0; cc < 6; ++cc) {
        float gv = g[cc];
        const float4* wr = reinterpret_cast<const float4*>(w1t + cc * 64);
#pragma unroll
        for (int o = 0; o < 64; o += 4) {
            float4 w = wr[o >> 2];
            h1[o]     += w.x * gv;
            h1[o + 1] += w.y * gv;
            h1[o + 2] += w.z * gv;
            h1[o + 3] += w.w * gv;
        }
    }
#pragma unroll
    for (int o = 0; o < 64; ++o) h1[o] = fmaxf(h1[o], 0.0f);

    // ---- fused layers 2+3 ----
    float h3[128];
#pragma unroll
    for (int o = 0; o < 128; o += 4) {
        float4 bv = *reinterpret_cast<const float4*>(b3s + o);
        h3[o] = bv.x; h3[o + 1] = bv.y; h3[o + 2] = bv.z; h3[o + 3] = bv.w;
    }

    for (int i = 0; i < 64; ++i) {
        const float4* w2r = reinterpret_cast<const float4*>(w2s + (i << 6));
        float a0 = 0.f, a1 = 0.f, a2 = 0.f, a3 = 0.f;
#pragma unroll
        for (int j = 0; j < 64; j += 16) {
            float4 wA = w2r[(j >> 2) + 0];
            float4 wB = w2r[(j >> 2) + 1];
            float4 wC = w2r[(j >> 2) + 2];
            float4 wD = w2r[(j >> 2) + 3];
            a0 += wA.x * h1[j + 0]  + wA.y * h1[j + 1]  + wA.z * h1[j + 2]  + wA.w * h1[j + 3];
            a1 += wB.x * h1[j + 4]  + wB.y * h1[j + 5]  + wB.z * h1[j + 6]  + wB.w * h1[j + 7];
            a2 += wC.x * h1[j + 8]  + wC.y * h1[j + 9]  + wC.z * h1[j + 10] + wC.w * h1[j + 11];
            a3 += wD.x * h1[j + 12] + wD.y * h1[j + 13] + wD.z * h1[j + 14] + wD.w * h1[j + 15];
        }
        float h2i = fmaxf(((a0 + a1) + (a2 + a3)) + b2s[i], 0.0f);

        const float4* w3r = reinterpret_cast<const float4*>(w3t + i * 132);
#pragma unroll
        for (int o = 0; o < 128; o += 4) {
            float4 w = w3r[o >> 2];
            h3[o]     += w.x * h2i;
            h3[o + 1] += w.y * h2i;
            h3[o + 2] += w.z * h2i;
            h3[o + 3] += w.w * h2i;
        }
    }

#pragma unroll
    for (int o = 0; o < 128; ++o) h3[o] = fmaxf(h3[o], 0.0f);

    // ---- max over 64 samples (2 warps per center) ----
#pragma unroll
    for (int o = 0; o < 128; ++o) {
#pragma unroll
        for (int off = 16; off > 0; off >>= 1)
            h3[o] = fmaxf(h3[o], __shfl_down_sync(0xffffffffu, h3[o], off));
    }
    __shared__ float red[4][128];
    const int wid = tid >> 5, lane = tid & 31;
    if (lane == 0) {
#pragma unroll
        for (int o = 0; o < 128; ++o) red[wid][o] = h3[o];
    }
    __syncthreads();
    for (int t = tid; t < 256; t += 128) {
        int cc = t >> 7, oo = t & 127;
        float v = fmaxf(red[2 * cc][oo], red[2 * cc + 1][oo]);
        int ctr = blockIdx.x * 2 + cc;
        int bb = ctr >> 10, pp = ctr & 1023;
        out_feat[(size_t)bb * (128 * Pn) + (size_t)oo * Pn + pp] = v;
    }
}

// ---------------------------------------------------------------------------
// Launch: fps -> ball query -> group+MLP. Output = [new_xyz | new_features].
// ---------------------------------------------------------------------------
extern "C" void kernel_launch(void* const* d_in, const int* in_sizes, int n_in,
                              void* d_out, int out_size)
{
    (void)in_sizes; (void)n_in; (void)out_size;

    const float* xyz      = (const float*)d_in[0];
    const float* features = (const float*)d_in[1];
    const float* W1 = (const float*)d_in[2];
    const float* b1 = (const float*)d_in[3];
    const float* W2 = (const float*)d_in[4];
    const float* b2 = (const float*)d_in[5];
    const float* W3 = (const float*)d_in[6];
    const float* b3 = (const float*)d_in[7];

    float* out      = (float*)d_out;
    float* new_xyz  = out;                         // (B, P, 3)
    float* out_feat = out + (size_t)Bn * Pn * 3;   // (B, 128, P)

    const int fps_smem = 3 * Nn * (int)sizeof(float);         // 196608
    const int mlp_smem = SW_FLOATS * (int)sizeof(float);      // 52736

    cudaFuncSetAttribute(fps_kernel,
                         cudaFuncAttributeMaxDynamicSharedMemorySize, fps_smem);
    cudaFuncSetAttribute(group_mlp_kernel,
                         cudaFuncAttributeMaxDynamicSharedMemorySize, mlp_smem);

    fps_kernel<<<Bn, 1024, fps_smem>>>(xyz, new_xyz);
    ballq_kernel<<<(Bn * Pn) / 8, 256>>>(xyz, new_xyz);
    group_mlp_kernel<<<(Bn * Pn) / 2, 128, mlp_smem>>>(
        xyz, features, W1, b1, W2, b2, W3, b3, new_xyz, out_feat);
}

// round 6
// speedup vs baseline: 1.5050x; 1.5050x over previous
#include <cuda_runtime.h>

// Problem constants (fixed shapes from the reference)
constexpr int Bn = 4;       // batch
constexpr int Nn = 16384;   // points per cloud
constexpr int Pn = 1024;    // npoint (FPS samples)
constexpr int Sn = 64;      // nsample (ball query)

// Scratch: ball query indices (B,P,S). 1 MB.
__device__ int g_ball_idx[Bn * Pn * Sn];

// ---- packed f32x2 helpers (sm_100+). Per-lane semantics identical to
// __fadd_rn / __fmul_rn, so FPS distances stay bit-exact vs the scalar path.
typedef unsigned long long ull;
__device__ __forceinline__ ull pk2(float lo, float hi) {
    ull r; asm("mov.b64 %0,{%1,%2};" : "=l"(r) : "f"(lo), "f"(hi)); return r;
}
__device__ __forceinline__ void upk2(ull v, float& lo, float& hi) {
    asm("mov.b64 {%0,%1},%2;" : "=f"(lo), "=f"(hi) : "l"(v));
}
__device__ __forceinline__ ull addx2(ull a, ull b) {
    ull r; asm("add.rn.f32x2 %0,%1,%2;" : "=l"(r) : "l"(a), "l"(b)); return r;
}
__device__ __forceinline__ ull mulx2(ull a, ull b) {
    ull r; asm("mul.rn.f32x2 %0,%1,%2;" : "=l"(r) : "l"(a), "l"(b)); return r;
}

// ---------------------------------------------------------------------------
// Kernel 1: Furthest Point Sampling — one block (512 threads) per batch.
// Thread t owns 32 points p = m*512 + t (m = 0..31), processed as 16 packed
// pairs (m=2j, 2j+1). x,y live in packed registers; z in smem (packed pairs).
// mindist[32] in registers. Inner loop tracks only the value max; the argmax
// index is recovered by a block-max-gated equality scan + atomicMin on the
// global index (ties -> smallest index, matching jnp.argmax exactly).
// A float2 smem copy of (x,y) exists only for the 1-per-iter broadcast read.
// ---------------------------------------------------------------------------
constexpr int FPS_NT = 512;
constexpr int FPS_SMEM = Nn * 8 /*sxy*/ + (Nn / 2) * 8 /*szp*/ + 128;

__global__ __launch_bounds__(FPS_NT, 1)
void fps_kernel(const float* __restrict__ xyz, float* __restrict__ new_xyz)
{
    const int b = blockIdx.x;
    const float* pts = xyz + (size_t)b * Nn * 3;

    extern __shared__ float sm[];
    float2* sxy = reinterpret_cast<float2*>(sm);        // [Nn] broadcast copy
    ull*    szp = reinterpret_cast<ull*>(sm + 2 * Nn);  // [Nn/2] z pairs
    float*  s_wmax = sm + 2 * Nn + Nn;                  // [16]
    float*  s_bmax = s_wmax + 16;
    int*    s_sel  = reinterpret_cast<int*>(s_bmax + 1);

    const int tid  = threadIdx.x;
    const int lane = tid & 31;
    const int wid  = tid >> 5;

    // Stage: x,y into packed regs; z into packed smem; (x,y) copy for bcast.
    ull rx[16], ry[16];
#pragma unroll
    for (int j = 0; j < 16; ++j) {
        const int pA = (2 * j) * FPS_NT + tid;
        const int pB = pA + FPS_NT;
        float xA = pts[pA * 3 + 0], yA = pts[pA * 3 + 1], zA = pts[pA * 3 + 2];
        float xB = pts[pB * 3 + 0], yB = pts[pB * 3 + 1], zB = pts[pB * 3 + 2];
        rx[j] = pk2(xA, xB);
        ry[j] = pk2(yA, yB);
        szp[j * FPS_NT + tid] = pk2(zA, zB);
        sxy[pA] = make_float2(xA, yA);
        sxy[pB] = make_float2(xB, yB);
    }

    float md[32];
#pragma unroll
    for (int k = 0; k < 32; ++k) md[k] = 1e10f;   // matches jnp 1e10 init

    __syncthreads();

    // First selected point is index 0.
    float qx = sxy[0].x, qy = sxy[0].y, qz;
    { float zl, zh; upk2(szp[0], zl, zh); qz = zl; }
    if (tid == 0) {
        float* o = new_xyz + (size_t)b * Pn * 3;
        o[0] = qx; o[1] = qy; o[2] = qz;
    }

    for (int it = 1; it < Pn; ++it) {
        const ull nqx = pk2(-qx, -qx);
        const ull nqy = pk2(-qy, -qy);
        const ull nqz = pk2(-qz, -qz);

        float vm0 = -1.0f, vm1 = -1.0f;
#pragma unroll
        for (int j = 0; j < 16; ++j) {
            ull zp = szp[j * FPS_NT + tid];
            ull dx = addx2(rx[j], nqx);            // == __fadd_rn(x, -qx)
            ull dy = addx2(ry[j], nqy);
            ull dz = addx2(zp,    nqz);
            ull s  = addx2(addx2(mulx2(dx, dx), mulx2(dy, dy)), mulx2(dz, dz));
            float d0, d1; upk2(s, d0, d1);
            md[2 * j]     = fminf(md[2 * j],     d0);
            md[2 * j + 1] = fminf(md[2 * j + 1], d1);
            vm0 = fmaxf(vm0, md[2 * j]);
            vm1 = fmaxf(vm1, md[2 * j + 1]);
        }
        const float vmax = fmaxf(vm0, vm1);

        // warp butterfly max (value only)
        float w = vmax;
#pragma unroll
        for (int off = 16; off > 0; off >>= 1)
            w = fmaxf(w, __shfl_xor_sync(0xffffffffu, w, off));
        if (lane == 0) s_wmax[wid] = w;
        __syncthreads();

        if (wid == 0) {
            float bw = (lane < 16) ? s_wmax[lane] : -1e30f;
#pragma unroll
            for (int off = 16; off > 0; off >>= 1)
                bw = fmaxf(bw, __shfl_xor_sync(0xffffffffu, bw, off));
            if (lane == 0) { *s_bmax = bw; *s_sel = 0x7fffffff; }
        }
        __syncthreads();

        const float bmax = *s_bmax;
        if (vmax == bmax) {                       // winner thread(s) only
            int bk = 0;
#pragma unroll
            for (int m = 31; m >= 0; --m)
                if (md[m] == bmax) bk = m;        // smallest matching m
            atomicMin(s_sel, bk * FPS_NT + tid);  // smallest global index
        }
        __syncthreads();

        const int sel = *s_sel;
        float2 qv = sxy[sel];                     // smem broadcast read
        qx = qv.x; qy = qv.y;
        const int m = sel >> 9, t = sel & (FPS_NT - 1);
        float zl, zh; upk2(szp[(m >> 1) * FPS_NT + t], zl, zh);
        qz = (m & 1) ? zh : zl;
        if (tid == 0) {
            float* o = new_xyz + ((size_t)b * Pn + it) * 3;
            o[0] = qx; o[1] = qy; o[2] = qz;
        }
    }
}

// ---------------------------------------------------------------------------
// Kernel 2: Ball query — one warp per center, 8 centers (same batch) per block.
// First nsample in-ball indices in ascending order; pad with first hit (0 if
// none). Early exit once 64 found. Exact (non-contracted) distance + strict <.
// ---------------------------------------------------------------------------
__global__ __launch_bounds__(256)
void ballq_kernel(const float* __restrict__ xyz, const float* __restrict__ new_xyz)
{
    const int wglobal = blockIdx.x * 8 + (threadIdx.x >> 5);  // center id 0..4095
    const int b    = wglobal >> 10;
    const int lane = threadIdx.x & 31;

    const float* pts = xyz + (size_t)b * Nn * 3;
    const float* c   = new_xyz + (size_t)wglobal * 3;
    const float cx = c[0], cy = c[1], cz = c[2];
    int* oidx = g_ball_idx + (size_t)wglobal * Sn;

    const float R2 = (float)(0.3 * 0.3);   // same double->f32 path as JAX

    int  cnt   = 0;
    int  first = 0;
    bool have  = false;

    for (int base = 0; base < Nn; base += 32) {
        const int j = base + lane;
        float x = pts[j * 3 + 0];
        float y = pts[j * 3 + 1];
        float z = pts[j * 3 + 2];
        float dx = __fadd_rn(cx, -x);
        float dy = __fadd_rn(cy, -y);
        float dz = __fadd_rn(cz, -z);
        float d  = __fadd_rn(__fadd_rn(__fmul_rn(dx, dx), __fmul_rn(dy, dy)),
                             __fmul_rn(dz, dz));
        bool in = d < R2;
        unsigned m = __ballot_sync(0xffffffffu, in);
        if (m) {
            if (!have) { first = base + (__ffs(m) - 1); have = true; }
            if (in) {
                int pos = cnt + __popc(m & ((1u << lane) - 1u));
                if (pos < Sn) oidx[pos] = j;
            }
            cnt += __popc(m);
            if (cnt >= Sn) break;
        }
    }
    if (cnt < Sn) {
        for (int s = cnt + lane; s < Sn; s += 32) oidx[s] = first;  // 0 if none
    }
}

// ---------------------------------------------------------------------------
// Kernel 3: gather + MLP(6->64->64->128, relu) + max over samples.
// Block = 128 threads = 2 centers, thread = one sample.
// Weights in smem (W1,W3 transposed; W3 rows padded to 132 floats for
// conflict-free transpose + 16B-aligned float4 broadcast reads).
// Layers 2+3 fused: h2_i consumed immediately, h1[64]+h3[128] in registers.
// ---------------------------------------------------------------------------
constexpr int SW_FLOATS = 384 + 64 + 4096 + 64 + 64 * 132 + 128;  // 13184

__global__ __launch_bounds__(128)
void group_mlp_kernel(const float* __restrict__ xyz, const float* __restrict__ features,
                      const float* __restrict__ W1, const float* __restrict__ b1,
                      const float* __restrict__ W2, const float* __restrict__ b2,
                      const float* __restrict__ W3, const float* __restrict__ b3,
                      const float* __restrict__ new_xyz, float* __restrict__ out_feat)
{
    extern __shared__ float sw[];
    float* w1t = sw;                 // [6][64]   w1t[c*64+o] = W1[o][c]
    float* b1s = w1t + 384;          // [64]
    float* w2s = b1s + 64;           // [64][64]  row i = W2[i][:]
    float* b2s = w2s + 4096;         // [64]
    float* w3t = b2s + 64;           // [64][132] w3t[i*132+o] = W3[o][i]
    float* b3s = w3t + 64 * 132;     // [128]

    const int tid = threadIdx.x;

    for (int j = tid; j < 384; j += 128) {
        int cc = j >> 6, o = j & 63;
        w1t[j] = W1[o * 6 + cc];
    }
    if (tid < 64)  b1s[tid] = b1[tid];
    for (int j = tid; j < 4096; j += 128) w2s[j] = W2[j];
    if (tid < 64)  b2s[tid] = b2[tid];
    for (int j = tid; j < 8192; j += 128) {          // coalesced read, ~4-way STS
        int i = j & 63, o = j >> 6;
        w3t[i * 132 + o] = W3[j];
    }
    if (tid < 128) b3s[tid] = b3[tid];
    __syncthreads();

    const int cl = tid >> 6;                  // which of the 2 centers
    const int s  = tid & 63;                  // sample id
    const int center = blockIdx.x * 2 + cl;
    const int b  = center >> 10;
    const int gi = g_ball_idx[center * Sn + s];

    const float* pb = xyz      + (size_t)b * Nn * 3;
    const float* fb = features + (size_t)b * Nn * 3;
    const float* c  = new_xyz  + (size_t)center * 3;

    float g[6];
    g[0] = pb[gi * 3 + 0] - c[0];
    g[1] = pb[gi * 3 + 1] - c[1];
    g[2] = pb[gi * 3 + 2] - c[2];
    g[3] = fb[gi * 3 + 0];
    g[4] = fb[gi * 3 + 1];
    g[5] = fb[gi * 3 + 2];

    // ---- layer 1 ----
    float h1[64];
#pragma unroll
    for (int o = 0; o < 64; o += 4) {
        float4 bv = *reinterpret_cast<const float4*>(b1s + o);
        h1[o] = bv.x; h1[o + 1] = bv.y; h1[o + 2] = bv.z; h1[o + 3] = bv.w;
    }
#pragma unroll
    for (int cc = 0; cc < 6; ++cc) {
        float gv = g[cc];
        const float4* wr = reinterpret_cast<const float4*>(w1t + cc * 64);
#pragma unroll
        for (int o = 0; o < 64; o += 4) {
            float4 w = wr[o >> 2];
            h1[o]     += w.x * gv;
            h1[o + 1] += w.y * gv;
            h1[o + 2] += w.z * gv;
            h1[o + 3] += w.w * gv;
        }
    }
#pragma unroll
    for (int o = 0; o < 64; ++o) h1[o] = fmaxf(h1[o], 0.0f);

    // ---- fused layers 2+3 ----
    float h3[128];
#pragma unroll
    for (int o = 0; o < 128; o += 4) {
        float4 bv = *reinterpret_cast<const float4*>(b3s + o);
        h3[o] = bv.x; h3[o + 1] = bv.y; h3[o + 2] = bv.z; h3[o + 3] = bv.w;
    }

    for (int i = 0; i < 64; ++i) {
        const float4* w2r = reinterpret_cast<const float4*>(w2s + (i << 6));
        float a0 = 0.f, a1 = 0.f, a2 = 0.f, a3 = 0.f;
#pragma unroll
        for (int j = 0; j < 64; j += 16) {
            float4 wA = w2r[(j >> 2) + 0];
            float4 wB = w2r[(j >> 2) + 1];
            float4 wC = w2r[(j >> 2) + 2];
            float4 wD = w2r[(j >> 2) + 3];
            a0 += wA.x * h1[j + 0]  + wA.y * h1[j + 1]  + wA.z * h1[j + 2]  + wA.w * h1[j + 3];
            a1 += wB.x * h1[j + 4]  + wB.y * h1[j + 5]  + wB.z * h1[j + 6]  + wB.w * h1[j + 7];
            a2 += wC.x * h1[j + 8]  + wC.y * h1[j + 9]  + wC.z * h1[j + 10] + wC.w * h1[j + 11];
            a3 += wD.x * h1[j + 12] + wD.y * h1[j + 13] + wD.z * h1[j + 14] + wD.w * h1[j + 15];
        }
        float h2i = fmaxf(((a0 + a1) + (a2 + a3)) + b2s[i], 0.0f);

        const float4* w3r = reinterpret_cast<const float4*>(w3t + i * 132);
#pragma unroll
        for (int o = 0; o < 128; o += 4) {
            float4 w = w3r[o >> 2];
            h3[o]     += w.x * h2i;
            h3[o + 1] += w.y * h2i;
            h3[o + 2] += w.z * h2i;
            h3[o + 3] += w.w * h2i;
        }
    }

#pragma unroll
    for (int o = 0; o < 128; ++o) h3[o] = fmaxf(h3[o], 0.0f);

    // ---- max over 64 samples (2 warps per center) ----
#pragma unroll
    for (int o = 0; o < 128; ++o) {
#pragma unroll
        for (int off = 16; off > 0; off >>= 1)
            h3[o] = fmaxf(h3[o], __shfl_down_sync(0xffffffffu, h3[o], off));
    }
    __shared__ float red[4][128];
    const int wid = tid >> 5, lane = tid & 31;
    if (lane == 0) {
#pragma unroll
        for (int o = 0; o < 128; ++o) red[wid][o] = h3[o];
    }
    __syncthreads();
    for (int t = tid; t < 256; t += 128) {
        int cc = t >> 7, oo = t & 127;
        float v = fmaxf(red[2 * cc][oo], red[2 * cc + 1][oo]);
        int ctr = blockIdx.x * 2 + cc;
        int bb = ctr >> 10, pp = ctr & 1023;
        out_feat[(size_t)bb * (128 * Pn) + (size_t)oo * Pn + pp] = v;
    }
}

// ---------------------------------------------------------------------------
// Launch: fps -> ball query -> group+MLP. Output = [new_xyz | new_features].
// ---------------------------------------------------------------------------
extern "C" void kernel_launch(void* const* d_in, const int* in_sizes, int n_in,
                              void* d_out, int out_size)
{
    (void)in_sizes; (void)n_in; (void)out_size;

    const float* xyz      = (const float*)d_in[0];
    const float* features = (const float*)d_in[1];
    const float* W1 = (const float*)d_in[2];
    const float* b1 = (const float*)d_in[3];
    const float* W2 = (const float*)d_in[4];
    const float* b2 = (const float*)d_in[5];
    const float* W3 = (const float*)d_in[6];
    const float* b3 = (const float*)d_in[7];

    float* out      = (float*)d_out;
    float* new_xyz  = out;                         // (B, P, 3)
    float* out_feat = out + (size_t)Bn * Pn * 3;   // (B, 128, P)

    const int mlp_smem = SW_FLOATS * (int)sizeof(float);      // 52736

    cudaFuncSetAttribute(fps_kernel,
                         cudaFuncAttributeMaxDynamicSharedMemorySize, FPS_SMEM);
    cudaFuncSetAttribute(group_mlp_kernel,
                         cudaFuncAttributeMaxDynamicSharedMemorySize, mlp_smem);

    fps_kernel<<<Bn, FPS_NT, FPS_SMEM>>>(xyz, new_xyz);
    ballq_kernel<<<(Bn * Pn) / 8, 256>>>(xyz, new_xyz);
    group_mlp_kernel<<<(Bn * Pn) / 2, 128, mlp_smem>>>(
        xyz, features, W1, b1, W2, b2, W3, b3, new_xyz, out_feat);
}

// round 7
// speedup vs baseline: 1.6424x; 1.0913x over previous
#include <cuda_runtime.h>

// Problem constants (fixed shapes from the reference)
constexpr int Bn = 4;       // batch
constexpr int Nn = 16384;   // points per cloud
constexpr int Pn = 1024;    // npoint (FPS samples)
constexpr int Sn = 64;      // nsample (ball query)

// Scratch: ball query indices (B,P,S). 1 MB.
__device__ int g_ball_idx[Bn * Pn * Sn];

// ---- packed f32x2 helpers (sm_100+). Per-lane semantics identical to
// __fadd_rn / __fmul_rn, so FPS distances stay bit-exact vs the scalar path.
typedef unsigned long long ull;
__device__ __forceinline__ ull pk2(float lo, float hi) {
    ull r; asm("mov.b64 %0,{%1,%2};" : "=l"(r) : "f"(lo), "f"(hi)); return r;
}
__device__ __forceinline__ void upk2(ull v, float& lo, float& hi) {
    asm("mov.b64 {%0,%1},%2;" : "=f"(lo), "=f"(hi) : "l"(v));
}
__device__ __forceinline__ ull addx2(ull a, ull b) {
    ull r; asm("add.rn.f32x2 %0,%1,%2;" : "=l"(r) : "l"(a), "l"(b)); return r;
}
__device__ __forceinline__ ull mulx2(ull a, ull b) {
    ull r; asm("mul.rn.f32x2 %0,%1,%2;" : "=l"(r) : "l"(a), "l"(b)); return r;
}

// ---------------------------------------------------------------------------
// Kernel 1: Furthest Point Sampling — 4-CTA cluster per batch.
// Each CTA (512 threads) owns 4096 points fully in registers (packed f32x2
// x/y/z pairs) and keeps a full-cloud coord copy in smem for the per-iter
// broadcast of the selected point. Cross-CTA argmax: packed (dist,~idx) key
// via double-buffered DSMEM mailboxes + one barrier.cluster per iteration.
// Tie-breaking everywhere = smallest global index (matches jnp.argmax).
// ---------------------------------------------------------------------------
constexpr int FPS_CL   = 4;                 // CTAs per batch (cluster size)
constexpr int FPS_PART = Nn / FPS_CL;       // 4096 points per CTA
constexpr int FPS_NT   = 512;               // threads per CTA
constexpr int FPS_PPT  = FPS_PART / FPS_NT; // 8 points per thread
constexpr int FPS_NPAIR = FPS_PPT / 2;      // 4 packed pairs per thread
// smem: float2 sxy[Nn] + float szf[Nn] + 16 wmax + sel + pad + mbox[2][4]
constexpr int FPS_SMEM = (3 * Nn + 16 + 8 + 16) * 4;   // 196768 bytes

__global__ __launch_bounds__(FPS_NT, 1) __cluster_dims__(FPS_CL, 1, 1)
void fps_kernel(const float* __restrict__ xyz, float* __restrict__ new_xyz)
{
    const int b = blockIdx.x / FPS_CL;
    const int r = blockIdx.x % FPS_CL;     // cluster rank
    const float* pts = xyz + (size_t)b * Nn * 3;

    extern __shared__ float sm[];
    float2* sxy    = reinterpret_cast<float2*>(sm);   // [Nn]
    float*  szf    = sm + 2 * Nn;                     // [Nn]
    float*  s_wmax = sm + 3 * Nn;                     // [16]
    int*    s_sel  = reinterpret_cast<int*>(s_wmax + 16);
    ull*    mbox   = reinterpret_cast<ull*>(s_wmax + 24);  // [2][FPS_CL]

    const int tid  = threadIdx.x;
    const int lane = tid & 31;
    const int wid  = tid >> 5;

    // Stage the full cloud into this CTA's smem (for broadcasts).
    for (int p = tid; p < Nn; p += FPS_NT) {
        float x = pts[p * 3 + 0];
        float y = pts[p * 3 + 1];
        float z = pts[p * 3 + 2];
        sxy[p] = make_float2(x, y);
        szf[p] = z;
    }
    if (tid == 0) *s_sel = 0x7fffffff;
    __syncthreads();

    // This CTA's 4096-point partition -> registers, packed pairs.
    // Slot m (0..7) <-> global index base + m*FPS_NT + tid; pair j packs
    // slots (j, j+NPAIR) so slot order == ascending global index per thread.
    const int base = r * FPS_PART;
    ull rx[FPS_NPAIR], ry[FPS_NPAIR], rz[FPS_NPAIR];
#pragma unroll
    for (int j = 0; j < FPS_NPAIR; ++j) {
        const int pA = base + j * FPS_NT + tid;
        const int pB = pA + FPS_NPAIR * FPS_NT;
        float2 a = sxy[pA], c = sxy[pB];
        rx[j] = pk2(a.x, c.x);
        ry[j] = pk2(a.y, c.y);
        rz[j] = pk2(szf[pA], szf[pB]);
    }
    float md[FPS_PPT];
#pragma unroll
    for (int k = 0; k < FPS_PPT; ++k) md[k] = 1e10f;   // matches jnp 1e10 init

    // First selected point is index 0.
    float qx = sxy[0].x, qy = sxy[0].y, qz = szf[0];
    if (r == 0 && tid == 0) {
        float* o = new_xyz + (size_t)b * Pn * 3;
        o[0] = qx; o[1] = qy; o[2] = qz;
    }

    const unsigned mb_base =
        (unsigned)__cvta_generic_to_shared(mbox) + (unsigned)(r * 8);

    for (int it = 1; it < Pn; ++it) {
        const ull nqx = pk2(-qx, -qx);
        const ull nqy = pk2(-qy, -qy);
        const ull nqz = pk2(-qz, -qz);

        float vm0 = -1.0f, vm1 = -1.0f;
#pragma unroll
        for (int j = 0; j < FPS_NPAIR; ++j) {
            ull dx = addx2(rx[j], nqx);            // == __fadd_rn(x, -qx)
            ull dy = addx2(ry[j], nqy);
            ull dz = addx2(rz[j], nqz);
            ull s  = addx2(addx2(mulx2(dx, dx), mulx2(dy, dy)), mulx2(dz, dz));
            float d0, d1; upk2(s, d0, d1);
            md[j]             = fminf(md[j],             d0);
            md[j + FPS_NPAIR] = fminf(md[j + FPS_NPAIR], d1);
            vm0 = fmaxf(vm0, md[j]);
            vm1 = fmaxf(vm1, md[j + FPS_NPAIR]);
        }
        const float vmax = fmaxf(vm0, vm1);

        // warp butterfly max (value only)
        float w = vmax;
#pragma unroll
        for (int off = 16; off > 0; off >>= 1)
            w = fmaxf(w, __shfl_xor_sync(0xffffffffu, w, off));
        if (lane == 0) s_wmax[wid] = w;
        __syncthreads();

        // CTA max: every thread reduces the 16 warp maxima itself (no 2nd
        // barrier, no serialized warp-0 phase).
        const float4* wm4 = reinterpret_cast<const float4*>(s_wmax);
        float4 m0 = wm4[0], m1 = wm4[1], m2 = wm4[2], m3 = wm4[3];
        float cmax = fmaxf(fmaxf(fmaxf(m0.x, m0.y), fmaxf(m0.z, m0.w)),
                           fmaxf(fmaxf(m1.x, m1.y), fmaxf(m1.z, m1.w)));
        cmax = fmaxf(cmax,
                     fmaxf(fmaxf(fmaxf(m2.x, m2.y), fmaxf(m2.z, m2.w)),
                           fmaxf(fmaxf(m3.x, m3.y), fmaxf(m3.z, m3.w))));

        if (vmax == cmax) {                        // winner thread(s) only
            int bk = 0;
#pragma unroll
            for (int m = FPS_PPT - 1; m >= 0; --m)
                if (md[m] == cmax) bk = m;         // smallest matching slot
            atomicMin(s_sel, base + bk * FPS_NT + tid);  // smallest global idx
        }
        __syncthreads();

        const int buf = it & 1;
        if (tid == 0) {
            const int loc = *s_sel;
            *s_sel = 0x7fffffff;                   // reset for next iter
            const ull key = ((ull)__float_as_uint(cmax) << 32)
                          | (unsigned)(0xFFFF - loc);
            const unsigned slot = mb_base + (unsigned)(buf * FPS_CL * 8);
#pragma unroll
            for (int dst = 0; dst < FPS_CL; ++dst) {
                unsigned rem;
                asm volatile("mapa.shared::cluster.u32 %0, %1, %2;"
                             : "=r"(rem) : "r"(slot), "r"(dst));
                asm volatile("st.shared::cluster.u64 [%0], %1;"
                             :: "r"(rem), "l"(key) : "memory");
            }
        }
        asm volatile("barrier.cluster.arrive.aligned;" ::: "memory");
        asm volatile("barrier.cluster.wait.aligned;"   ::: "memory");

        // Winner across CTAs: max packed key (max dist, then min index).
        const ull* mb = mbox + buf * FPS_CL;
        ull k0 = mb[0], k1 = mb[1], k2 = mb[2], k3 = mb[3];
        ull kk = k0 > k1 ? k0 : k1;
        ull kl = k2 > k3 ? k2 : k3;
        kk = kk > kl ? kk : kl;
        const int sel = 0xFFFF - (int)(unsigned)kk;

        float2 qv = sxy[sel];                      // local smem broadcast
        qx = qv.x; qy = qv.y; qz = szf[sel];
        if (r == 0 && tid == 0) {
            float* o = new_xyz + ((size_t)b * Pn + it) * 3;
            o[0] = qx; o[1] = qy; o[2] = qz;
        }
    }
}

// ---------------------------------------------------------------------------
// Kernel 2: Ball query — one warp per center, 8 centers (same batch) per block.
// First nsample in-ball indices in ascending order; pad with first hit (0 if
// none). Early exit once 64 found. Exact (non-contracted) distance + strict <.
// ---------------------------------------------------------------------------
__global__ __launch_bounds__(256)
void ballq_kernel(const float* __restrict__ xyz, const float* __restrict__ new_xyz)
{
    const int wglobal = blockIdx.x * 8 + (threadIdx.x >> 5);  // center id 0..4095
    const int b    = wglobal >> 10;
    const int lane = threadIdx.x & 31;

    const float* pts = xyz + (size_t)b * Nn * 3;
    const float* c   = new_xyz + (size_t)wglobal * 3;
    const float cx = c[0], cy = c[1], cz = c[2];
    int* oidx = g_ball_idx + (size_t)wglobal * Sn;

    const float R2 = (float)(0.3 * 0.3);   // same double->f32 path as JAX

    int  cnt   = 0;
    int  first = 0;
    bool have  = false;

    for (int base = 0; base < Nn; base += 32) {
        const int j = base + lane;
        float x = pts[j * 3 + 0];
        float y = pts[j * 3 + 1];
        float z = pts[j * 3 + 2];
        float dx = __fadd_rn(cx, -x);
        float dy = __fadd_rn(cy, -y);
        float dz = __fadd_rn(cz, -z);
        float d  = __fadd_rn(__fadd_rn(__fmul_rn(dx, dx), __fmul_rn(dy, dy)),
                             __fmul_rn(dz, dz));
        bool in = d < R2;
        unsigned m = __ballot_sync(0xffffffffu, in);
        if (m) {
            if (!have) { first = base + (__ffs(m) - 1); have = true; }
            if (in) {
                int pos = cnt + __popc(m & ((1u << lane) - 1u));
                if (pos < Sn) oidx[pos] = j;
            }
            cnt += __popc(m);
            if (cnt >= Sn) break;
        }
    }
    if (cnt < Sn) {
        for (int s = cnt + lane; s < Sn; s += 32) oidx[s] = first;  // 0 if none
    }
}

// ---------------------------------------------------------------------------
// Kernel 3: gather + MLP(6->64->64->128, relu) + max over samples.
// Block = 128 threads = 2 centers, thread = one sample.
// Weights in smem (W1,W3 transposed; W3 rows padded to 132 floats for
// conflict-free transpose + 16B-aligned float4 broadcast reads).
// Layers 2+3 fused: h2_i consumed immediately, h1[64]+h3[128] in registers.
// ---------------------------------------------------------------------------
constexpr int SW_FLOATS = 384 + 64 + 4096 + 64 + 64 * 132 + 128;  // 13184

__global__ __launch_bounds__(128)
void group_mlp_kernel(const float* __restrict__ xyz, const float* __restrict__ features,
                      const float* __restrict__ W1, const float* __restrict__ b1,
                      const float* __restrict__ W2, const float* __restrict__ b2,
                      const float* __restrict__ W3, const float* __restrict__ b3,
                      const float* __restrict__ new_xyz, float* __restrict__ out_feat)
{
    extern __shared__ float sw[];
    float* w1t = sw;                 // [6][64]   w1t[c*64+o] = W1[o][c]
    float* b1s = w1t + 384;          // [64]
    float* w2s = b1s + 64;           // [64][64]  row i = W2[i][:]
    float* b2s = w2s + 4096;         // [64]
    float* w3t = b2s + 64;           // [64][132] w3t[i*132+o] = W3[o][i]
    float* b3s = w3t + 64 * 132;     // [128]

    const int tid = threadIdx.x;

    for (int j = tid; j < 384; j += 128) {
        int cc = j >> 6, o = j & 63;
        w1t[j] = W1[o * 6 + cc];
    }
    if (tid < 64)  b1s[tid] = b1[tid];
    for (int j = tid; j < 4096; j += 128) w2s[j] = W2[j];
    if (tid < 64)  b2s[tid] = b2[tid];
    for (int j = tid; j < 8192; j += 128) {          // coalesced read, ~4-way STS
        int i = j & 63, o = j >> 6;
        w3t[i * 132 + o] = W3[j];
    }
    if (tid < 128) b3s[tid] = b3[tid];
    __syncthreads();

    const int cl = tid >> 6;                  // which of the 2 centers
    const int s  = tid & 63;                  // sample id
    const int center = blockIdx.x * 2 + cl;
    const int b  = center >> 10;
    const int gi = g_ball_idx[center * Sn + s];

    const float* pb = xyz      + (size_t)b * Nn * 3;
    const float* fb = features + (size_t)b * Nn * 3;
    const float* c  = new_xyz  + (size_t)center * 3;

    float g[6];
    g[0] = pb[gi * 3 + 0] - c[0];
    g[1] = pb[gi * 3 + 1] - c[1];
    g[2] = pb[gi * 3 + 2] - c[2];
    g[3] = fb[gi * 3 + 0];
    g[4] = fb[gi * 3 + 1];
    g[5] = fb[gi * 3 + 2];

    // ---- layer 1 ----
    float h1[64];
#pragma unroll
    for (int o = 0; o < 64; o += 4) {
        float4 bv = *reinterpret_cast<const float4*>(b1s + o);
        h1[o] = bv.x; h1[o + 1] = bv.y; h1[o + 2] = bv.z; h1[o + 3] = bv.w;
    }
#pragma unroll
    for (int cc = 0; cc < 6; ++cc) {
        float gv = g[cc];
        const float4* wr = reinterpret_cast<const float4*>(w1t + cc * 64);
#pragma unroll
        for (int o = 0; o < 64; o += 4) {
            float4 w = wr[o >> 2];
            h1[o]     += w.x * gv;
            h1[o + 1] += w.y * gv;
            h1[o + 2] += w.z * gv;
            h1[o + 3] += w.w * gv;
        }
    }
#pragma unroll
    for (int o = 0; o < 64; ++o) h1[o] = fmaxf(h1[o], 0.0f);

    // ---- fused layers 2+3 ----
    float h3[128];
#pragma unroll
    for (int o = 0; o < 128; o += 4) {
        float4 bv = *reinterpret_cast<const float4*>(b3s + o);
        h3[o] = bv.x; h3[o + 1] = bv.y; h3[o + 2] = bv.z; h3[o + 3] = bv.w;
    }

    for (int i = 0; i < 64; ++i) {
        const float4* w2r = reinterpret_cast<const float4*>(w2s + (i << 6));
        float a0 = 0.f, a1 = 0.f, a2 = 0.f, a3 = 0.f;
#pragma unroll
        for (int j = 0; j < 64; j += 16) {
            float4 wA = w2r[(j >> 2) + 0];
            float4 wB = w2r[(j >> 2) + 1];
            float4 wC = w2r[(j >> 2) + 2];
            float4 wD = w2r[(j >> 2) + 3];
            a0 += wA.x * h1[j + 0]  + wA.y * h1[j + 1]  + wA.z * h1[j + 2]  + wA.w * h1[j + 3];
            a1 += wB.x * h1[j + 4]  + wB.y * h1[j + 5]  + wB.z * h1[j + 6]  + wB.w * h1[j + 7];
            a2 += wC.x * h1[j + 8]  + wC.y * h1[j + 9]  + wC.z * h1[j + 10] + wC.w * h1[j + 11];
            a3 += wD.x * h1[j + 12] + wD.y * h1[j + 13] + wD.z * h1[j + 14] + wD.w * h1[j + 15];
        }
        float h2i = fmaxf(((a0 + a1) + (a2 + a3)) + b2s[i], 0.0f);

        const float4* w3r = reinterpret_cast<const float4*>(w3t + i * 132);
#pragma unroll
        for (int o = 0; o < 128; o += 4) {
            float4 w = w3r[o >> 2];
            h3[o]     += w.x * h2i;
            h3[o + 1] += w.y * h2i;
            h3[o + 2] += w.z * h2i;
            h3[o + 3] += w.w * h2i;
        }
    }

#pragma unroll
    for (int o = 0; o < 128; ++o) h3[o] = fmaxf(h3[o], 0.0f);

    // ---- max over 64 samples (2 warps per center) ----
#pragma unroll
    for (int o = 0; o < 128; ++o) {
#pragma unroll
        for (int off = 16; off > 0; off >>= 1)
            h3[o] = fmaxf(h3[o], __shfl_down_sync(0xffffffffu, h3[o], off));
    }
    __shared__ float red[4][128];
    const int wid = tid >> 5, lane = tid & 31;
    if (lane == 0) {
#pragma unroll
        for (int o = 0; o < 128; ++o) red[wid][o] = h3[o];
    }
    __syncthreads();
    for (int t = tid; t < 256; t += 128) {
        int cc = t >> 7, oo = t & 127;
        float v = fmaxf(red[2 * cc][oo], red[2 * cc + 1][oo]);
        int ctr = blockIdx.x * 2 + cc;
        int bb = ctr >> 10, pp = ctr & 1023;
        out_feat[(size_t)bb * (128 * Pn) + (size_t)oo * Pn + pp] = v;
    }
}

// ---------------------------------------------------------------------------
// Launch: fps (clustered) -> ball query -> group+MLP.
// Output = [new_xyz | new_features].
// ---------------------------------------------------------------------------
extern "C" void kernel_launch(void* const* d_in, const int* in_sizes, int n_in,
                              void* d_out, int out_size)
{
    (void)in_sizes; (void)n_in; (void)out_size;

    const float* xyz      = (const float*)d_in[0];
    const float* features = (const float*)d_in[1];
    const float* W1 = (const float*)d_in[2];
    const float* b1 = (const float*)d_in[3];
    const float* W2 = (const float*)d_in[4];
    const float* b2 = (const float*)d_in[5];
    const float* W3 = (const float*)d_in[6];
    const float* b3 = (const float*)d_in[7];

    float* out      = (float*)d_out;
    float* new_xyz  = out;                         // (B, P, 3)
    float* out_feat = out + (size_t)Bn * Pn * 3;   // (B, 128, P)

    const int mlp_smem = SW_FLOATS * (int)sizeof(float);      // 52736

    cudaFuncSetAttribute(fps_kernel,
                         cudaFuncAttributeMaxDynamicSharedMemorySize, FPS_SMEM);
    cudaFuncSetAttribute(group_mlp_kernel,
                         cudaFuncAttributeMaxDynamicSharedMemorySize, mlp_smem);

    fps_kernel<<<Bn * FPS_CL, FPS_NT, FPS_SMEM>>>(xyz, new_xyz);
    ballq_kernel<<<(Bn * Pn) / 8, 256>>>(xyz, new_xyz);
    group_mlp_kernel<<<(Bn * Pn) / 2, 128, mlp_smem>>>(
        xyz, features, W1, b1, W2, b2, W3, b3, new_xyz, out_feat);
}